// round 2
// baseline (speedup 1.0000x reference)
#include <cuda_runtime.h>
#include <math.h>

#define B_SZ   512
#define T_MAXV 200
#define HID    1024
#define MLPH   1024
#define OUTD   256

// ---------------- device scratch (no allocation allowed) ----------------
__device__ float g_x[B_SZ * OUTD];            // current input x_t  [512,256]
__device__ float g_h[B_SZ * HID];             // GRU hidden        [512,1024]
__device__ float g_u[B_SZ * 2 * MLPH];        // tanh(MLP hidden)  [512,2048] (u1 | u2)
__device__ float g_pp[2][B_SZ][2 * OUTD];     // split-K partials  [2,512,512] (p1 | p2)
__device__ int   g_bs[T_MAXV];                // batch_sizes[t]
__device__ int   g_offs[T_MAXV + 1];          // exclusive prefix sum of bs

__device__ __forceinline__ float sigmoidf_(float v) { return 1.0f / (1.0f + expf(-v)); }

// ---------------- per-launch setup ----------------
__global__ void precompute_kernel(const int* __restrict__ lengths) {
    int t = threadIdx.x;
    if (t < T_MAXV) {
        int c = 0;
        #pragma unroll 8
        for (int b = 0; b < B_SZ; ++b) c += (lengths[b] > t) ? 1 : 0;
        g_bs[t] = c;
    }
    __syncthreads();
    if (t == 0) {
        int acc = 0;
        for (int i = 0; i < T_MAXV; ++i) { g_offs[i] = acc; acc += g_bs[i]; }
        g_offs[T_MAXV] = acc;
    }
}

__global__ void zero_x_kernel() {
    int i = blockIdx.x * blockDim.x + threadIdx.x;
    if (i < B_SZ * OUTD) g_x[i] = 0.0f;
}

// ---------------- stage 1: GRU gates + h ----------------
// gi = x @ W_ih^T ; r=sig(gi_r+bhr), z=sig(gi_z+bhz), n=tanh(gi_n+r*bhn), h=(1-z)*n
// grid (HID/64=16, B/64=8), 256 threads, 64x64 tile, K=256, 3 weight tiles.
__global__ void __launch_bounds__(256) gru_kernel(
    const float* __restrict__ W_ih, const float* __restrict__ b_ih,
    const float* __restrict__ b_hh, float* __restrict__ out_h, int t)
{
    const int bs_t = g_bs[t];
    const int m0 = blockIdx.y * 64;
    if (m0 >= bs_t) return;
    const int n0 = blockIdx.x * 64;

    __shared__ float As[32][68];
    __shared__ float Br[32][68];
    __shared__ float Bz[32][68];
    __shared__ float Bn[32][68];

    const int tid = threadIdx.x;
    const int tx = tid & 15;       // n quadrant (x4)
    const int ty = tid >> 4;       // m quadrant (x4)

    float accR[4][4] = {}, accZ[4][4] = {}, accN[4][4] = {};

    const float* Wr = W_ih + (size_t)n0 * OUTD;
    const float* Wz = W_ih + (size_t)(HID + n0) * OUTD;
    const float* Wn = W_ih + (size_t)(2 * HID + n0) * OUTD;

    for (int k0 = 0; k0 < OUTD; k0 += 32) {
        #pragma unroll
        for (int i = 0; i < 2; ++i) {
            int idx = tid + i * 256;      // 0..511
            int r = idx >> 3;             // 0..63
            int c = (idx & 7) << 2;       // 0..28 step 4
            float4 va = *reinterpret_cast<const float4*>(&g_x[(m0 + r) * OUTD + k0 + c]);
            As[c + 0][r] = va.x; As[c + 1][r] = va.y; As[c + 2][r] = va.z; As[c + 3][r] = va.w;
            float4 vr = *reinterpret_cast<const float4*>(&Wr[(size_t)r * OUTD + k0 + c]);
            Br[c + 0][r] = vr.x; Br[c + 1][r] = vr.y; Br[c + 2][r] = vr.z; Br[c + 3][r] = vr.w;
            float4 vz = *reinterpret_cast<const float4*>(&Wz[(size_t)r * OUTD + k0 + c]);
            Bz[c + 0][r] = vz.x; Bz[c + 1][r] = vz.y; Bz[c + 2][r] = vz.z; Bz[c + 3][r] = vz.w;
            float4 vn = *reinterpret_cast<const float4*>(&Wn[(size_t)r * OUTD + k0 + c]);
            Bn[c + 0][r] = vn.x; Bn[c + 1][r] = vn.y; Bn[c + 2][r] = vn.z; Bn[c + 3][r] = vn.w;
        }
        __syncthreads();
        #pragma unroll
        for (int k = 0; k < 32; ++k) {
            float4 a4 = *reinterpret_cast<const float4*>(&As[k][ty * 4]);
            float4 r4 = *reinterpret_cast<const float4*>(&Br[k][tx * 4]);
            float4 z4 = *reinterpret_cast<const float4*>(&Bz[k][tx * 4]);
            float4 n4 = *reinterpret_cast<const float4*>(&Bn[k][tx * 4]);
            const float a[4]  = {a4.x, a4.y, a4.z, a4.w};
            const float br[4] = {r4.x, r4.y, r4.z, r4.w};
            const float bz[4] = {z4.x, z4.y, z4.z, z4.w};
            const float bn[4] = {n4.x, n4.y, n4.z, n4.w};
            #pragma unroll
            for (int i = 0; i < 4; ++i)
                #pragma unroll
                for (int j = 0; j < 4; ++j) {
                    accR[i][j] = fmaf(a[i], br[j], accR[i][j]);
                    accZ[i][j] = fmaf(a[i], bz[j], accZ[i][j]);
                    accN[i][j] = fmaf(a[i], bn[j], accN[i][j]);
                }
        }
        __syncthreads();
    }

    const int off_t = g_offs[t];
    #pragma unroll
    for (int i = 0; i < 4; ++i) {
        const int m = m0 + ty * 4 + i;
        #pragma unroll
        for (int j = 0; j < 4; ++j) {
            const int n = n0 + tx * 4 + j;
            float r  = sigmoidf_(accR[i][j] + b_ih[n]           + b_hh[n]);
            float z  = sigmoidf_(accZ[i][j] + b_ih[HID + n]     + b_hh[HID + n]);
            float nn = tanhf   (accN[i][j] + b_ih[2 * HID + n] + r * b_hh[2 * HID + n]);
            float h  = (1.0f - z) * nn;
            g_h[m * HID + n] = h;
            if (m < bs_t) out_h[(size_t)(off_t + m) * HID + n] = h;
        }
    }
}

// ---------------- stage 2: u = tanh(h @ [W1a;W2a]^T + b) ----------------
// grid (2048/64=32, B/64=8), 256 threads, 64x64x32 tiles, K=1024.
__global__ void __launch_bounds__(256) mlp_hidden_kernel(
    const float* __restrict__ W1a, const float* __restrict__ b1a,
    const float* __restrict__ W2a, const float* __restrict__ b2a, int t)
{
    const int bs_t = g_bs[t];
    const int m0 = blockIdx.y * 64;
    if (m0 >= bs_t) return;
    const int n0 = blockIdx.x * 64;   // 0..2047

    const float* W; const float* ba; int nl;
    if (n0 < MLPH) { W = W1a + (size_t)n0 * HID;          ba = b1a; nl = n0; }
    else           { W = W2a + (size_t)(n0 - MLPH) * HID; ba = b2a; nl = n0 - MLPH; }

    __shared__ float As[32][68];
    __shared__ float Bs[32][68];

    const int tid = threadIdx.x;
    const int tx = tid & 15;
    const int ty = tid >> 4;

    float acc[4][4] = {};

    for (int k0 = 0; k0 < HID; k0 += 32) {
        #pragma unroll
        for (int i = 0; i < 2; ++i) {
            int idx = tid + i * 256;
            int r = idx >> 3;
            int c = (idx & 7) << 2;
            float4 va = *reinterpret_cast<const float4*>(&g_h[(m0 + r) * HID + k0 + c]);
            As[c + 0][r] = va.x; As[c + 1][r] = va.y; As[c + 2][r] = va.z; As[c + 3][r] = va.w;
            float4 vb = *reinterpret_cast<const float4*>(&W[(size_t)r * HID + k0 + c]);
            Bs[c + 0][r] = vb.x; Bs[c + 1][r] = vb.y; Bs[c + 2][r] = vb.z; Bs[c + 3][r] = vb.w;
        }
        __syncthreads();
        #pragma unroll
        for (int k = 0; k < 32; ++k) {
            float4 a4 = *reinterpret_cast<const float4*>(&As[k][ty * 4]);
            float4 b4 = *reinterpret_cast<const float4*>(&Bs[k][tx * 4]);
            const float a[4] = {a4.x, a4.y, a4.z, a4.w};
            const float b[4] = {b4.x, b4.y, b4.z, b4.w};
            #pragma unroll
            for (int i = 0; i < 4; ++i)
                #pragma unroll
                for (int j = 0; j < 4; ++j)
                    acc[i][j] = fmaf(a[i], b[j], acc[i][j]);
        }
        __syncthreads();
    }

    #pragma unroll
    for (int i = 0; i < 4; ++i) {
        const int m = m0 + ty * 4 + i;
        #pragma unroll
        for (int j = 0; j < 4; ++j) {
            const int n = n0 + tx * 4 + j;
            g_u[m * (2 * MLPH) + n] = tanhf(acc[i][j] + ba[nl + tx * 4 + j]);
        }
    }
}

// ---------------- stage 3a: p1/p2 GEMM with split-K=2 ----------------
// logical C[512, 512]: cols 0..255 -> p1 (u1 . W1b), cols 256..511 -> p2 (u2 . W2b)
// grid (512/64=8, B/64=8, 2), 256 threads. Each z computes K/2=512 slice.
__global__ void __launch_bounds__(256) mlp_out_gemm_kernel(
    const float* __restrict__ W1b, const float* __restrict__ W2b, int t)
{
    const int bs_t = g_bs[t];
    const int m0 = blockIdx.y * 64;
    if (m0 >= bs_t) return;
    const int n0 = blockIdx.x * 64;   // 0..511
    const int z  = blockIdx.z;        // k split

    const float* W; int sel;
    if (n0 < OUTD) { W = W1b + (size_t)n0 * MLPH;          sel = 0; }
    else           { W = W2b + (size_t)(n0 - OUTD) * MLPH; sel = 1; }
    const int akbase = sel * MLPH + z * 512;   // column base in g_u
    const int wkbase = z * 512;                // column base in W

    __shared__ float As[32][68];
    __shared__ float Bs[32][68];

    const int tid = threadIdx.x;
    const int tx = tid & 15;
    const int ty = tid >> 4;

    float acc[4][4] = {};

    for (int k0 = 0; k0 < 512; k0 += 32) {
        #pragma unroll
        for (int i = 0; i < 2; ++i) {
            int idx = tid + i * 256;
            int r = idx >> 3;
            int c = (idx & 7) << 2;
            float4 va = *reinterpret_cast<const float4*>(&g_u[(m0 + r) * (2 * MLPH) + akbase + k0 + c]);
            As[c + 0][r] = va.x; As[c + 1][r] = va.y; As[c + 2][r] = va.z; As[c + 3][r] = va.w;
            float4 vb = *reinterpret_cast<const float4*>(&W[(size_t)r * MLPH + wkbase + k0 + c]);
            Bs[c + 0][r] = vb.x; Bs[c + 1][r] = vb.y; Bs[c + 2][r] = vb.z; Bs[c + 3][r] = vb.w;
        }
        __syncthreads();
        #pragma unroll
        for (int k = 0; k < 32; ++k) {
            float4 a4 = *reinterpret_cast<const float4*>(&As[k][ty * 4]);
            float4 b4 = *reinterpret_cast<const float4*>(&Bs[k][tx * 4]);
            const float a[4] = {a4.x, a4.y, a4.z, a4.w};
            const float b[4] = {b4.x, b4.y, b4.z, b4.w};
            #pragma unroll
            for (int i = 0; i < 4; ++i)
                #pragma unroll
                for (int j = 0; j < 4; ++j)
                    acc[i][j] = fmaf(a[i], b[j], acc[i][j]);
        }
        __syncthreads();
    }

    #pragma unroll
    for (int i = 0; i < 4; ++i) {
        const int m = m0 + ty * 4 + i;
        #pragma unroll
        for (int j = 0; j < 4; ++j) {
            const int n = n0 + tx * 4 + j;
            g_pp[z][m][n] = acc[i][j];
        }
    }
}

// ---------------- stage 3b: combine split-K, reparam sample, scatter ----------------
__global__ void combine_kernel(
    const float* __restrict__ b1b, const float* __restrict__ b2b,
    const float* __restrict__ eps,
    float* __restrict__ out_p1, float* __restrict__ out_p2, int t)
{
    const int m = blockIdx.x;       // 0..511
    const int n = threadIdx.x;      // 0..255
    const int bs_t = g_bs[t];
    if (m >= bs_t) return;
    float p1 = g_pp[0][m][n]        + g_pp[1][m][n]        + b1b[n];
    float p2 = g_pp[0][m][n + OUTD] + g_pp[1][m][n + OUTD] + b2b[n];
    float e  = eps[((size_t)t * B_SZ + m) * OUTD + n];
    g_x[m * OUTD + n] = p1 + expf(0.5f * p2) * e;
    const int row = g_offs[t] + m;
    out_p1[(size_t)row * OUTD + n] = p1;
    out_p2[(size_t)row * OUTD + n] = p2;
}

// ---------------- launch ----------------
extern "C" void kernel_launch(void* const* d_in, const int* in_sizes, int n_in,
                              void* d_out, int out_size) {
    const int*   lengths = (const int*)  d_in[1];
    const float* eps     = (const float*)d_in[2];
    const float* W_ih    = (const float*)d_in[5];
    const float* b_ih    = (const float*)d_in[6];
    const float* b_hh    = (const float*)d_in[8];
    const float* W1a     = (const float*)d_in[9];
    const float* b1a     = (const float*)d_in[10];
    const float* W1b     = (const float*)d_in[11];
    const float* b1b     = (const float*)d_in[12];
    const float* W2a     = (const float*)d_in[13];
    const float* b2a     = (const float*)d_in[14];
    const float* W2b     = (const float*)d_in[15];
    const float* b2b     = (const float*)d_in[16];

    float* out = (float*)d_out;
    const long long N = (long long)out_size / (2 * OUTD + HID);
    float* out_p1 = out;
    float* out_p2 = out + N * OUTD;
    float* out_h  = out + 2LL * N * OUTD;

    precompute_kernel<<<1, 256>>>(lengths);
    zero_x_kernel<<<512, 256>>>();

    for (int t = 0; t < T_MAXV; ++t) {
        gru_kernel<<<dim3(16, 8), 256>>>(W_ih, b_ih, b_hh, out_h, t);
        mlp_hidden_kernel<<<dim3(32, 8), 256>>>(W1a, b1a, W2a, b2a, t);
        mlp_out_gemm_kernel<<<dim3(8, 8, 2), 256>>>(W1b, W2b, t);
        combine_kernel<<<512, 256>>>(b1b, b2b, eps, out_p1, out_p2, t);
    }
}

// round 3
// speedup vs baseline: 1.2801x; 1.2801x over previous
#include <cuda_runtime.h>
#include <cuda_bf16.h>
#include <math.h>
#include <stdint.h>

#define HIDN   1024
#define MLPH   1024
#define OUTD   256
#define B_SZ   512
#define T_MAXV 200
#define SST    40     // smem row stride in bf16 elems (32 data + 8 pad)

// ------------------- device scratch (static, no allocation) -------------------
__device__ __align__(16) __nv_bfloat16 gXhi[B_SZ*OUTD],   gXlo[B_SZ*OUTD];
__device__ __align__(16) __nv_bfloat16 gHhi[B_SZ*HIDN],   gHlo[B_SZ*HIDN];
__device__ __align__(16) __nv_bfloat16 gUhi[B_SZ*2*MLPH], gUlo[B_SZ*2*MLPH];
__device__ __align__(16) __nv_bfloat16 gWih_h[3*HIDN*OUTD], gWih_l[3*HIDN*OUTD];
__device__ __align__(16) __nv_bfloat16 gW1a_h[MLPH*HIDN],   gW1a_l[MLPH*HIDN];
__device__ __align__(16) __nv_bfloat16 gW2a_h[MLPH*HIDN],   gW2a_l[MLPH*HIDN];
__device__ __align__(16) __nv_bfloat16 gW1b_h[OUTD*MLPH],   gW1b_l[OUTD*MLPH];
__device__ __align__(16) __nv_bfloat16 gW2b_h[OUTD*MLPH],   gW2b_l[OUTD*MLPH];
__device__ int g_bs[T_MAXV];
__device__ int g_offs[T_MAXV + 1];

__device__ __forceinline__ float sigmoidf_(float v) { return 1.0f / (1.0f + expf(-v)); }

__device__ __forceinline__ void split_store(__nv_bfloat16* hi, __nv_bfloat16* lo, int idx, float v) {
    __nv_bfloat16 h = __float2bfloat16(v);
    hi[idx] = h;
    lo[idx] = __float2bfloat16(v - __bfloat162float(h));
}

// ------------------- setup kernels -------------------
__global__ void precompute_kernel(const int* __restrict__ lengths) {
    int t = threadIdx.x;
    if (t < T_MAXV) {
        int c = 0;
        #pragma unroll 8
        for (int b = 0; b < B_SZ; ++b) c += (lengths[b] > t) ? 1 : 0;
        g_bs[t] = c;
    }
    __syncthreads();
    if (t == 0) {
        int acc = 0;
        for (int i = 0; i < T_MAXV; ++i) { g_offs[i] = acc; acc += g_bs[i]; }
        g_offs[T_MAXV] = acc;
    }
}

__global__ void zero_x_kernel() {
    int i = blockIdx.x * blockDim.x + threadIdx.x;
    if (i < B_SZ * OUTD) { gXhi[i] = __float2bfloat16(0.0f); gXlo[i] = __float2bfloat16(0.0f); }
}

// Convert all weights fp32 -> bf16 hi/lo (once per launch; weights are loop-invariant)
#define N_WIH  (3*HIDN*OUTD)        // 786432
#define N_W1A  (MLPH*HIDN)          // 1048576
#define N_W1B  (OUTD*MLPH)          // 262144
#define N_ALL  (N_WIH + 2*N_W1A + 2*N_W1B)
__global__ void convert_all_kernel(const float* __restrict__ Wih,
                                   const float* __restrict__ W1a, const float* __restrict__ W2a,
                                   const float* __restrict__ W1b, const float* __restrict__ W2b) {
    int i = blockIdx.x * 256 + threadIdx.x;
    if (i >= N_ALL) return;
    const float* src; __nv_bfloat16* hi; __nv_bfloat16* lo; int j = i;
    if (j < N_WIH)                { src = Wih; hi = gWih_h; lo = gWih_l; }
    else if ((j -= N_WIH) < N_W1A){ src = W1a; hi = gW1a_h; lo = gW1a_l; }
    else if ((j -= N_W1A) < N_W1A){ src = W2a; hi = gW2a_h; lo = gW2a_l; }
    else if ((j -= N_W1A) < N_W1B){ src = W1b; hi = gW1b_h; lo = gW1b_l; }
    else { j -= N_W1B;              src = W2b; hi = gW2b_h; lo = gW2b_l; }
    float v = src[j];
    __nv_bfloat16 h = __float2bfloat16(v);
    hi[j] = h;
    lo[j] = __float2bfloat16(v - __bfloat162float(h));
}

// ------------------- MMA primitives -------------------
__device__ __forceinline__ uint32_t s2u(const void* p) { return (uint32_t)__cvta_generic_to_shared(p); }

__device__ __forceinline__ void ldm4(uint32_t* r, const __nv_bfloat16* p) {
    uint32_t a = s2u(p);
    asm volatile("ldmatrix.sync.aligned.m8n8.x4.shared.b16 {%0,%1,%2,%3}, [%4];"
                 : "=r"(r[0]), "=r"(r[1]), "=r"(r[2]), "=r"(r[3]) : "r"(a));
}

__device__ __forceinline__ void mma16816(float* c, const uint32_t* a, uint32_t b0, uint32_t b1) {
    asm volatile("mma.sync.aligned.m16n8k16.row.col.f32.bf16.bf16.f32 "
                 "{%0,%1,%2,%3},{%4,%5,%6,%7},{%8,%9},{%0,%1,%2,%3};"
                 : "+f"(c[0]), "+f"(c[1]), "+f"(c[2]), "+f"(c[3])
                 : "r"(a[0]), "r"(a[1]), "r"(a[2]), "r"(a[3]), "r"(b0), "r"(b1));
}

// ------------------- tile movement (64 rows x 32 cols bf16) -------------------
__device__ __forceinline__ void copy_tile(__nv_bfloat16* dst, const __nv_bfloat16* src, int ld, int tid) {
    #pragma unroll
    for (int i = 0; i < 2; ++i) {
        int idx = tid + i * 128;
        int r = idx >> 2, cv = (idx & 3) * 8;
        *reinterpret_cast<uint4*>(dst + r * SST + cv) =
            *reinterpret_cast<const uint4*>(src + (size_t)r * ld + cv);
    }
}
__device__ __forceinline__ void ld_tile(uint4* rg, const __nv_bfloat16* src, int ld, int tid) {
    #pragma unroll
    for (int i = 0; i < 2; ++i) {
        int idx = tid + i * 128;
        int r = idx >> 2, cv = (idx & 3) * 8;
        rg[i] = *reinterpret_cast<const uint4*>(src + (size_t)r * ld + cv);
    }
}
__device__ __forceinline__ void st_tile(__nv_bfloat16* dst, const uint4* rg, int tid) {
    #pragma unroll
    for (int i = 0; i < 2; ++i) {
        int idx = tid + i * 128;
        int r = idx >> 2, cv = (idx & 3) * 8;
        *reinterpret_cast<uint4*>(dst + r * SST + cv) = rg[i];
    }
}

// ------------------- core 64x64 GEMM, double buffered, bf16x3 -------------------
// C[mi][j][e]: warp computes 32x32; block 64x64 via 4 warps (2x2).
__device__ __forceinline__ void gemm64_db(
    float C[2][4][4],
    const __nv_bfloat16* Ah, const __nv_bfloat16* Al, int ldA,
    const __nv_bfloat16* Bh, const __nv_bfloat16* Bl, int ldB,
    int nk, __nv_bfloat16 (*sm)[4][64 * SST], int tid)
{
    const int lane = tid & 31, warp = tid >> 5;
    const int wm = (warp & 1) * 32, wn = (warp >> 1) * 32;
    const int arow = lane & 15, acol = (lane & 16) >> 1;
    const int brow = (lane & 7) + ((lane & 16) >> 1), bcol = lane & 8;

    copy_tile(sm[0][0], Ah, ldA, tid);
    copy_tile(sm[0][1], Al, ldA, tid);
    copy_tile(sm[0][2], Bh, ldB, tid);
    copy_tile(sm[0][3], Bl, ldB, tid);
    __syncthreads();

    for (int kc = 0; kc < nk; ++kc) {
        uint4 rg[4][2];
        if (kc + 1 < nk) {
            ld_tile(rg[0], Ah + (kc + 1) * 32, ldA, tid);
            ld_tile(rg[1], Al + (kc + 1) * 32, ldA, tid);
            ld_tile(rg[2], Bh + (kc + 1) * 32, ldB, tid);
            ld_tile(rg[3], Bl + (kc + 1) * 32, ldB, tid);
        }
        const __nv_bfloat16* bAh = sm[kc & 1][0];
        const __nv_bfloat16* bAl = sm[kc & 1][1];
        const __nv_bfloat16* bBh = sm[kc & 1][2];
        const __nv_bfloat16* bBl = sm[kc & 1][3];

        #pragma unroll
        for (int ks = 0; ks < 32; ks += 16) {
            uint32_t ah[2][4], al[2][4], bh[2][4], bl[2][4];
            #pragma unroll
            for (int mi = 0; mi < 2; ++mi) {
                ldm4(ah[mi], bAh + (wm + mi * 16 + arow) * SST + ks + acol);
                ldm4(al[mi], bAl + (wm + mi * 16 + arow) * SST + ks + acol);
            }
            #pragma unroll
            for (int nb = 0; nb < 2; ++nb) {
                ldm4(bh[nb], bBh + (wn + nb * 16 + brow) * SST + ks + bcol);
                ldm4(bl[nb], bBl + (wn + nb * 16 + brow) * SST + ks + bcol);
            }
            #pragma unroll
            for (int mi = 0; mi < 2; ++mi)
                #pragma unroll
                for (int j = 0; j < 4; ++j) {
                    const int nb = j >> 1, p = (j & 1) * 2;
                    mma16816(C[mi][j], ah[mi], bh[nb][p], bh[nb][p + 1]);
                    mma16816(C[mi][j], ah[mi], bl[nb][p], bl[nb][p + 1]);
                    mma16816(C[mi][j], al[mi], bh[nb][p], bh[nb][p + 1]);
                }
        }
        if (kc + 1 < nk) {
            st_tile(sm[(kc + 1) & 1][0], rg[0], tid);
            st_tile(sm[(kc + 1) & 1][1], rg[1], tid);
            st_tile(sm[(kc + 1) & 1][2], rg[2], tid);
            st_tile(sm[(kc + 1) & 1][3], rg[3], tid);
        }
        __syncthreads();
    }
}

// ------------------- stage 1: GRU (x @ W_ih^T, 3 gates fused) -------------------
__global__ void __launch_bounds__(128) gru_mma(
    const float* __restrict__ b_ih, const float* __restrict__ b_hh,
    float* __restrict__ out_h, int t)
{
    const int bs_t = g_bs[t];
    const int m0 = blockIdx.y * 64;
    if (m0 >= bs_t) return;
    const int n0 = blockIdx.x * 64;

    __shared__ __nv_bfloat16 sm1[8][64 * SST];  // Ah,Al,B0h,B0l,B1h,B1l,B2h,B2l

    const int tid = threadIdx.x;
    const int lane = tid & 31, warp = tid >> 5;
    const int wm = (warp & 1) * 32, wn = (warp >> 1) * 32;
    const int arow = lane & 15, acol = (lane & 16) >> 1;
    const int brow = (lane & 7) + ((lane & 16) >> 1), bcol = lane & 8;

    float C[3][2][4][4] = {};

    const __nv_bfloat16* Ah = gXhi + (size_t)m0 * OUTD;
    const __nv_bfloat16* Al = gXlo + (size_t)m0 * OUTD;

    for (int kc = 0; kc < OUTD / 32; ++kc) {
        copy_tile(sm1[0], Ah + kc * 32, OUTD, tid);
        copy_tile(sm1[1], Al + kc * 32, OUTD, tid);
        #pragma unroll
        for (int g = 0; g < 3; ++g) {
            const size_t wro = (size_t)(g * HIDN + n0) * OUTD + kc * 32;
            copy_tile(sm1[2 + 2 * g],     gWih_h + wro, OUTD, tid);
            copy_tile(sm1[2 + 2 * g + 1], gWih_l + wro, OUTD, tid);
        }
        __syncthreads();
        #pragma unroll
        for (int ks = 0; ks < 32; ks += 16) {
            uint32_t ah[2][4], al[2][4];
            #pragma unroll
            for (int mi = 0; mi < 2; ++mi) {
                ldm4(ah[mi], sm1[0] + (wm + mi * 16 + arow) * SST + ks + acol);
                ldm4(al[mi], sm1[1] + (wm + mi * 16 + arow) * SST + ks + acol);
            }
            #pragma unroll
            for (int g = 0; g < 3; ++g) {
                uint32_t bh[2][4], bl[2][4];
                #pragma unroll
                for (int nb = 0; nb < 2; ++nb) {
                    ldm4(bh[nb], sm1[2 + 2 * g]     + (wn + nb * 16 + brow) * SST + ks + bcol);
                    ldm4(bl[nb], sm1[2 + 2 * g + 1] + (wn + nb * 16 + brow) * SST + ks + bcol);
                }
                #pragma unroll
                for (int mi = 0; mi < 2; ++mi)
                    #pragma unroll
                    for (int j = 0; j < 4; ++j) {
                        const int nb = j >> 1, p = (j & 1) * 2;
                        mma16816(C[g][mi][j], ah[mi], bh[nb][p], bh[nb][p + 1]);
                        mma16816(C[g][mi][j], ah[mi], bl[nb][p], bl[nb][p + 1]);
                        mma16816(C[g][mi][j], al[mi], bh[nb][p], bh[nb][p + 1]);
                    }
            }
        }
        __syncthreads();
    }

    // epilogue: gates -> h, write h hi/lo + packed out_h
    const int g_ = lane >> 2, tg = lane & 3;
    const int off_t = g_offs[t];
    #pragma unroll
    for (int mi = 0; mi < 2; ++mi)
        #pragma unroll
        for (int j = 0; j < 4; ++j)
            #pragma unroll
            for (int e = 0; e < 4; ++e) {
                const int m = m0 + wm + mi * 16 + g_ + (e & 2) * 4;
                const int n = n0 + wn + j * 8 + tg * 2 + (e & 1);
                float r  = sigmoidf_(C[0][mi][j][e] + b_ih[n]            + b_hh[n]);
                float z  = sigmoidf_(C[1][mi][j][e] + b_ih[HIDN + n]     + b_hh[HIDN + n]);
                float nn = tanhf   (C[2][mi][j][e] + b_ih[2 * HIDN + n] + r * b_hh[2 * HIDN + n]);
                float h  = (1.0f - z) * nn;
                split_store(gHhi, gHlo, m * HIDN + n, h);
                if (m < bs_t) out_h[(size_t)(off_t + m) * HIDN + n] = h;
            }
}

// ------------------- stage 2: u = tanh(h @ [W1a;W2a]^T + b) -------------------
__global__ void __launch_bounds__(128) mlp_hidden_mma(
    const float* __restrict__ b1a, const float* __restrict__ b2a, int t)
{
    const int bs_t = g_bs[t];
    const int m0 = blockIdx.y * 64;
    if (m0 >= bs_t) return;
    const int n0 = blockIdx.x * 64;   // 0..2047

    __shared__ __nv_bfloat16 sm[2][4][64 * SST];
    const int tid = threadIdx.x;

    const __nv_bfloat16* Bh;
    const __nv_bfloat16* Bl;
    if (n0 < MLPH) { Bh = gW1a_h + (size_t)n0 * HIDN;          Bl = gW1a_l + (size_t)n0 * HIDN; }
    else           { Bh = gW2a_h + (size_t)(n0 - MLPH) * HIDN; Bl = gW2a_l + (size_t)(n0 - MLPH) * HIDN; }

    float C[2][4][4] = {};
    gemm64_db(C, gHhi + (size_t)m0 * HIDN, gHlo + (size_t)m0 * HIDN, HIDN,
              Bh, Bl, HIDN, HIDN / 32, sm, tid);

    const int lane = tid & 31, warp = tid >> 5;
    const int wm = (warp & 1) * 32, wn = (warp >> 1) * 32;
    const int g_ = lane >> 2, tg = lane & 3;
    #pragma unroll
    for (int mi = 0; mi < 2; ++mi)
        #pragma unroll
        for (int j = 0; j < 4; ++j)
            #pragma unroll
            for (int e = 0; e < 4; ++e) {
                const int m = m0 + wm + mi * 16 + g_ + (e & 2) * 4;
                const int nrel = wn + j * 8 + tg * 2 + (e & 1);
                const int ng = n0 + nrel;
                float bias = (n0 < MLPH) ? b1a[ng] : b2a[ng - MLPH];
                float u = tanhf(C[mi][j][e] + bias);
                split_store(gUhi, gUlo, m * (2 * MLPH) + ng, u);
            }
}

// ------------------- stage 3: p1/p2 + reparam sample + scatter -------------------
__global__ void __launch_bounds__(128) mlp_out_mma(
    const float* __restrict__ b1b, const float* __restrict__ b2b,
    const float* __restrict__ eps,
    float* __restrict__ out_p1, float* __restrict__ out_p2, int t)
{
    const int bs_t = g_bs[t];
    const int m0 = blockIdx.y * 64;
    if (m0 >= bs_t) return;
    const int n0 = blockIdx.x * 64;   // 0..255

    __shared__ __nv_bfloat16 sm[2][4][64 * SST];
    const int tid = threadIdx.x;

    float C1[2][4][4] = {};
    gemm64_db(C1, gUhi + (size_t)m0 * (2 * MLPH), gUlo + (size_t)m0 * (2 * MLPH), 2 * MLPH,
              gW1b_h + (size_t)n0 * MLPH, gW1b_l + (size_t)n0 * MLPH, MLPH,
              MLPH / 32, sm, tid);

    float C2[2][4][4] = {};
    gemm64_db(C2, gUhi + (size_t)m0 * (2 * MLPH) + MLPH, gUlo + (size_t)m0 * (2 * MLPH) + MLPH, 2 * MLPH,
              gW2b_h + (size_t)n0 * MLPH, gW2b_l + (size_t)n0 * MLPH, MLPH,
              MLPH / 32, sm, tid);

    const int lane = tid & 31, warp = tid >> 5;
    const int wm = (warp & 1) * 32, wn = (warp >> 1) * 32;
    const int g_ = lane >> 2, tg = lane & 3;
    const int off_t = g_offs[t];
    #pragma unroll
    for (int mi = 0; mi < 2; ++mi)
        #pragma unroll
        for (int j = 0; j < 4; ++j)
            #pragma unroll
            for (int e = 0; e < 4; ++e) {
                const int m = m0 + wm + mi * 16 + g_ + (e & 2) * 4;
                const int n = n0 + wn + j * 8 + tg * 2 + (e & 1);
                float p1 = C1[mi][j][e] + b1b[n];
                float p2 = C2[mi][j][e] + b2b[n];
                float x  = p1 + expf(0.5f * p2) * eps[((size_t)t * B_SZ + m) * OUTD + n];
                split_store(gXhi, gXlo, m * OUTD + n, x);
                if (m < bs_t) {
                    out_p1[(size_t)(off_t + m) * OUTD + n] = p1;
                    out_p2[(size_t)(off_t + m) * OUTD + n] = p2;
                }
            }
}

// ------------------- launch -------------------
extern "C" void kernel_launch(void* const* d_in, const int* in_sizes, int n_in,
                              void* d_out, int out_size) {
    const int*   lengths = (const int*)  d_in[1];
    const float* eps     = (const float*)d_in[2];
    const float* W_ih    = (const float*)d_in[5];
    const float* b_ih    = (const float*)d_in[6];
    const float* b_hh    = (const float*)d_in[8];
    const float* W1a     = (const float*)d_in[9];
    const float* b1a     = (const float*)d_in[10];
    const float* W1b     = (const float*)d_in[11];
    const float* b1b     = (const float*)d_in[12];
    const float* W2a     = (const float*)d_in[13];
    const float* b2a     = (const float*)d_in[14];
    const float* W2b     = (const float*)d_in[15];
    const float* b2b     = (const float*)d_in[16];

    float* out = (float*)d_out;
    const long long N = (long long)out_size / (2 * OUTD + HIDN);
    float* out_p1 = out;
    float* out_p2 = out + N * OUTD;
    float* out_h  = out + 2LL * N * OUTD;

    precompute_kernel<<<1, 256>>>(lengths);
    zero_x_kernel<<<512, 256>>>();
    convert_all_kernel<<<(N_ALL + 255) / 256, 256>>>(W_ih, W1a, W2a, W1b, W2b);

    for (int t = 0; t < T_MAXV; ++t) {
        gru_mma<<<dim3(16, 8), 128>>>(b_ih, b_hh, out_h, t);
        mlp_hidden_mma<<<dim3(32, 8), 128>>>(b1a, b2a, t);
        mlp_out_mma<<<dim3(4, 8), 128>>>(b1b, b2b, eps, out_p1, out_p2, t);
    }
}

// round 4
// speedup vs baseline: 2.0036x; 1.5652x over previous
#include <cuda_runtime.h>
#include <cuda_bf16.h>
#include <math.h>
#include <stdint.h>

#define HIDN   1024
#define MLPH   1024
#define OUTD   256
#define B_SZ   512
#define T_MAXV 200
#define SST    40     // smem row stride in bf16 elems (32 data + 8 pad)
#define ZK     4      // stage-3 split-K

// ------------------- device scratch (static, no allocation) -------------------
__device__ __align__(16) __nv_bfloat16 gXhi[B_SZ*OUTD],   gXlo[B_SZ*OUTD];
__device__ __align__(16) __nv_bfloat16 gHhi[B_SZ*HIDN],   gHlo[B_SZ*HIDN];
__device__ __align__(16) __nv_bfloat16 gUhi[B_SZ*2*MLPH], gUlo[B_SZ*2*MLPH];
__device__ __align__(16) __nv_bfloat16 gWih_h[3*HIDN*OUTD], gWih_l[3*HIDN*OUTD];
__device__ __align__(16) __nv_bfloat16 gW1a_h[MLPH*HIDN],   gW1a_l[MLPH*HIDN];
__device__ __align__(16) __nv_bfloat16 gW2a_h[MLPH*HIDN],   gW2a_l[MLPH*HIDN];
__device__ __align__(16) __nv_bfloat16 gW1b_h[OUTD*MLPH],   gW1b_l[OUTD*MLPH];
__device__ __align__(16) __nv_bfloat16 gW2b_h[OUTD*MLPH],   gW2b_l[OUTD*MLPH];
__device__ float g_pp[ZK][B_SZ][2*OUTD];   // stage-3 split-K partials (4 MB)
__device__ int g_bs[T_MAXV];
__device__ int g_offs[T_MAXV + 1];

__device__ __forceinline__ float sigmoidf_(float v) { return 1.0f / (1.0f + expf(-v)); }

__device__ __forceinline__ void split_store(__nv_bfloat16* hi, __nv_bfloat16* lo, int idx, float v) {
    __nv_bfloat16 h = __float2bfloat16(v);
    hi[idx] = h;
    lo[idx] = __float2bfloat16(v - __bfloat162float(h));
}

// ------------------- setup kernels -------------------
__global__ void precompute_kernel(const int* __restrict__ lengths) {
    int t = threadIdx.x;
    if (t < T_MAXV) {
        int c = 0;
        #pragma unroll 8
        for (int b = 0; b < B_SZ; ++b) c += (lengths[b] > t) ? 1 : 0;
        g_bs[t] = c;
    }
    __syncthreads();
    if (t == 0) {
        int acc = 0;
        for (int i = 0; i < T_MAXV; ++i) { g_offs[i] = acc; acc += g_bs[i]; }
        g_offs[T_MAXV] = acc;
    }
}

__global__ void zero_x_kernel() {
    int i = blockIdx.x * blockDim.x + threadIdx.x;
    if (i < B_SZ * OUTD) { gXhi[i] = __float2bfloat16(0.0f); gXlo[i] = __float2bfloat16(0.0f); }
}

#define N_WIH  (3*HIDN*OUTD)
#define N_W1A  (MLPH*HIDN)
#define N_W1B  (OUTD*MLPH)
#define N_ALL  (N_WIH + 2*N_W1A + 2*N_W1B)
__global__ void convert_all_kernel(const float* __restrict__ Wih,
                                   const float* __restrict__ W1a, const float* __restrict__ W2a,
                                   const float* __restrict__ W1b, const float* __restrict__ W2b) {
    int i = blockIdx.x * 256 + threadIdx.x;
    if (i >= N_ALL) return;
    const float* src; __nv_bfloat16* hi; __nv_bfloat16* lo; int j = i;
    if (j < N_WIH)                { src = Wih; hi = gWih_h; lo = gWih_l; }
    else if ((j -= N_WIH) < N_W1A){ src = W1a; hi = gW1a_h; lo = gW1a_l; }
    else if ((j -= N_W1A) < N_W1A){ src = W2a; hi = gW2a_h; lo = gW2a_l; }
    else if ((j -= N_W1A) < N_W1B){ src = W1b; hi = gW1b_h; lo = gW1b_l; }
    else { j -= N_W1B;              src = W2b; hi = gW2b_h; lo = gW2b_l; }
    float v = src[j];
    __nv_bfloat16 h = __float2bfloat16(v);
    hi[j] = h;
    lo[j] = __float2bfloat16(v - __bfloat162float(h));
}

// ------------------- async copy + MMA primitives -------------------
__device__ __forceinline__ void cp16(void* smem, const void* gmem) {
    uint32_t s = (uint32_t)__cvta_generic_to_shared(smem);
    asm volatile("cp.async.cg.shared.global [%0], [%1], 16;" :: "r"(s), "l"(gmem));
}
__device__ __forceinline__ void cp_commit() { asm volatile("cp.async.commit_group;"); }
__device__ __forceinline__ void cp_wait1()  { asm volatile("cp.async.wait_group 1;"); }
__device__ __forceinline__ void cp_wait0()  { asm volatile("cp.async.wait_group 0;"); }

__device__ __forceinline__ uint32_t s2u(const void* p) { return (uint32_t)__cvta_generic_to_shared(p); }

__device__ __forceinline__ void ldm4(uint32_t* r, const __nv_bfloat16* p) {
    uint32_t a = s2u(p);
    asm volatile("ldmatrix.sync.aligned.m8n8.x4.shared.b16 {%0,%1,%2,%3}, [%4];"
                 : "=r"(r[0]), "=r"(r[1]), "=r"(r[2]), "=r"(r[3]) : "r"(a));
}

__device__ __forceinline__ void mma16816(float* c, const uint32_t* a, uint32_t b0, uint32_t b1) {
    asm volatile("mma.sync.aligned.m16n8k16.row.col.f32.bf16.bf16.f32 "
                 "{%0,%1,%2,%3},{%4,%5,%6,%7},{%8,%9},{%0,%1,%2,%3};"
                 : "+f"(c[0]), "+f"(c[1]), "+f"(c[2]), "+f"(c[3])
                 : "r"(a[0]), "r"(a[1]), "r"(a[2]), "r"(a[3]), "r"(b0), "r"(b1));
}

// async copy of a 64-row x 32-col bf16 tile into smem (stride SST)
__device__ __forceinline__ void cpa_tile(__nv_bfloat16* dst, const __nv_bfloat16* src, int ld, int tid) {
    #pragma unroll
    for (int i = 0; i < 2; ++i) {
        int idx = tid + i * 128;
        int r = idx >> 2, c = (idx & 3) * 8;
        cp16(dst + r * SST + c, src + (size_t)r * ld + c);
    }
}

// ------------------- core 64x64 GEMM, cp.async double buffered, bf16x3 -------------------
__device__ __forceinline__ void gemm_ca(
    float C[2][4][4],
    const __nv_bfloat16* Ah, const __nv_bfloat16* Al, int ldA,
    const __nv_bfloat16* Bh, const __nv_bfloat16* Bl, int ldB,
    int nk, __nv_bfloat16 (*sm)[4][64 * SST], int tid)
{
    const int lane = tid & 31, warp = tid >> 5;
    const int wm = (warp & 1) * 32, wn = (warp >> 1) * 32;
    const int arow = lane & 15, acol = (lane & 16) >> 1;
    const int brow = (lane & 7) + ((lane & 16) >> 1), bcol = lane & 8;

    cpa_tile(sm[0][0], Ah, ldA, tid);
    cpa_tile(sm[0][1], Al, ldA, tid);
    cpa_tile(sm[0][2], Bh, ldB, tid);
    cpa_tile(sm[0][3], Bl, ldB, tid);
    cp_commit();

    for (int kc = 0; kc < nk; ++kc) {
        if (kc + 1 < nk) {
            __nv_bfloat16 (*nb)[64 * SST] = sm[(kc + 1) & 1];
            cpa_tile(nb[0], Ah + (kc + 1) * 32, ldA, tid);
            cpa_tile(nb[1], Al + (kc + 1) * 32, ldA, tid);
            cpa_tile(nb[2], Bh + (kc + 1) * 32, ldB, tid);
            cpa_tile(nb[3], Bl + (kc + 1) * 32, ldB, tid);
            cp_commit();
            cp_wait1();
        } else {
            cp_wait0();
        }
        __syncthreads();

        const __nv_bfloat16* bAh = sm[kc & 1][0];
        const __nv_bfloat16* bAl = sm[kc & 1][1];
        const __nv_bfloat16* bBh = sm[kc & 1][2];
        const __nv_bfloat16* bBl = sm[kc & 1][3];

        #pragma unroll
        for (int ks = 0; ks < 32; ks += 16) {
            uint32_t ah[2][4], al[2][4], bh[2][4], bl[2][4];
            #pragma unroll
            for (int mi = 0; mi < 2; ++mi) {
                ldm4(ah[mi], bAh + (wm + mi * 16 + arow) * SST + ks + acol);
                ldm4(al[mi], bAl + (wm + mi * 16 + arow) * SST + ks + acol);
            }
            #pragma unroll
            for (int nb2 = 0; nb2 < 2; ++nb2) {
                ldm4(bh[nb2], bBh + (wn + nb2 * 16 + brow) * SST + ks + bcol);
                ldm4(bl[nb2], bBl + (wn + nb2 * 16 + brow) * SST + ks + bcol);
            }
            #pragma unroll
            for (int mi = 0; mi < 2; ++mi)
                #pragma unroll
                for (int j = 0; j < 4; ++j) {
                    const int nb3 = j >> 1, p = (j & 1) * 2;
                    mma16816(C[mi][j], ah[mi], bh[nb3][p], bh[nb3][p + 1]);
                    mma16816(C[mi][j], ah[mi], bl[nb3][p], bl[nb3][p + 1]);
                    mma16816(C[mi][j], al[mi], bh[nb3][p], bh[nb3][p + 1]);
                }
        }
        __syncthreads();
    }
}

// ------------------- stage 1: GRU (x @ W_ih^T, 3 gates fused) -------------------
// dynamic smem: [2][8][64*SST] bf16 = 81920 bytes
__global__ void __launch_bounds__(128) gru_mma(
    const float* __restrict__ b_ih, const float* __restrict__ b_hh,
    float* __restrict__ out_h, int t)
{
    const int bs_t = g_bs[t];
    const int m0 = blockIdx.y * 64;
    if (m0 >= bs_t) return;
    const int n0 = blockIdx.x * 64;

    extern __shared__ __nv_bfloat16 smd[];
    __nv_bfloat16 (*sm)[8][64 * SST] = reinterpret_cast<__nv_bfloat16 (*)[8][64 * SST]>(smd);

    const int tid = threadIdx.x;
    const int lane = tid & 31, warp = tid >> 5;
    const int wm = (warp & 1) * 32, wn = (warp >> 1) * 32;
    const int arow = lane & 15, acol = (lane & 16) >> 1;
    const int brow = (lane & 7) + ((lane & 16) >> 1), bcol = lane & 8;

    float C[3][2][4][4] = {};

    const __nv_bfloat16* Ah = gXhi + (size_t)m0 * OUTD;
    const __nv_bfloat16* Al = gXlo + (size_t)m0 * OUTD;

    // prefetch chunk 0
    {
        cpa_tile(sm[0][0], Ah, OUTD, tid);
        cpa_tile(sm[0][1], Al, OUTD, tid);
        #pragma unroll
        for (int g = 0; g < 3; ++g) {
            const size_t wro = (size_t)(g * HIDN + n0) * OUTD;
            cpa_tile(sm[0][2 + 2 * g],     gWih_h + wro, OUTD, tid);
            cpa_tile(sm[0][2 + 2 * g + 1], gWih_l + wro, OUTD, tid);
        }
        cp_commit();
    }

    const int NKC = OUTD / 32;   // 8
    for (int kc = 0; kc < NKC; ++kc) {
        if (kc + 1 < NKC) {
            __nv_bfloat16 (*nbuf)[64 * SST] = sm[(kc + 1) & 1];
            const int ko = (kc + 1) * 32;
            cpa_tile(nbuf[0], Ah + ko, OUTD, tid);
            cpa_tile(nbuf[1], Al + ko, OUTD, tid);
            #pragma unroll
            for (int g = 0; g < 3; ++g) {
                const size_t wro = (size_t)(g * HIDN + n0) * OUTD + ko;
                cpa_tile(nbuf[2 + 2 * g],     gWih_h + wro, OUTD, tid);
                cpa_tile(nbuf[2 + 2 * g + 1], gWih_l + wro, OUTD, tid);
            }
            cp_commit();
            cp_wait1();
        } else {
            cp_wait0();
        }
        __syncthreads();

        __nv_bfloat16 (*buf)[64 * SST] = sm[kc & 1];
        #pragma unroll
        for (int ks = 0; ks < 32; ks += 16) {
            uint32_t ah[2][4], al[2][4];
            #pragma unroll
            for (int mi = 0; mi < 2; ++mi) {
                ldm4(ah[mi], buf[0] + (wm + mi * 16 + arow) * SST + ks + acol);
                ldm4(al[mi], buf[1] + (wm + mi * 16 + arow) * SST + ks + acol);
            }
            #pragma unroll
            for (int g = 0; g < 3; ++g) {
                uint32_t bh[2][4], bl[2][4];
                #pragma unroll
                for (int nb = 0; nb < 2; ++nb) {
                    ldm4(bh[nb], buf[2 + 2 * g]     + (wn + nb * 16 + brow) * SST + ks + bcol);
                    ldm4(bl[nb], buf[2 + 2 * g + 1] + (wn + nb * 16 + brow) * SST + ks + bcol);
                }
                #pragma unroll
                for (int mi = 0; mi < 2; ++mi)
                    #pragma unroll
                    for (int j = 0; j < 4; ++j) {
                        const int nb = j >> 1, p = (j & 1) * 2;
                        mma16816(C[g][mi][j], ah[mi], bh[nb][p], bh[nb][p + 1]);
                        mma16816(C[g][mi][j], ah[mi], bl[nb][p], bl[nb][p + 1]);
                        mma16816(C[g][mi][j], al[mi], bh[nb][p], bh[nb][p + 1]);
                    }
            }
        }
        __syncthreads();
    }

    // epilogue: gates -> h, write h hi/lo + packed out_h
    const int g_ = lane >> 2, tg = lane & 3;
    const int off_t = g_offs[t];
    #pragma unroll
    for (int mi = 0; mi < 2; ++mi)
        #pragma unroll
        for (int j = 0; j < 4; ++j)
            #pragma unroll
            for (int e = 0; e < 4; ++e) {
                const int m = m0 + wm + mi * 16 + g_ + (e & 2) * 4;
                const int n = n0 + wn + j * 8 + tg * 2 + (e & 1);
                float r  = sigmoidf_(C[0][mi][j][e] + b_ih[n]            + b_hh[n]);
                float z  = sigmoidf_(C[1][mi][j][e] + b_ih[HIDN + n]     + b_hh[HIDN + n]);
                float nn = tanhf   (C[2][mi][j][e] + b_ih[2 * HIDN + n] + r * b_hh[2 * HIDN + n]);
                float h  = (1.0f - z) * nn;
                split_store(gHhi, gHlo, m * HIDN + n, h);
                if (m < bs_t) out_h[(size_t)(off_t + m) * HIDN + n] = h;
            }
}

// ------------------- stage 2: u = tanh(h @ [W1a;W2a]^T + b) -------------------
__global__ void __launch_bounds__(128) mlp_hidden_mma(
    const float* __restrict__ b1a, const float* __restrict__ b2a, int t)
{
    const int bs_t = g_bs[t];
    const int m0 = blockIdx.y * 64;
    if (m0 >= bs_t) return;
    const int n0 = blockIdx.x * 64;   // 0..2047

    __shared__ __nv_bfloat16 sm[2][4][64 * SST];
    const int tid = threadIdx.x;

    const __nv_bfloat16* Bh;
    const __nv_bfloat16* Bl;
    if (n0 < MLPH) { Bh = gW1a_h + (size_t)n0 * HIDN;          Bl = gW1a_l + (size_t)n0 * HIDN; }
    else           { Bh = gW2a_h + (size_t)(n0 - MLPH) * HIDN; Bl = gW2a_l + (size_t)(n0 - MLPH) * HIDN; }

    float C[2][4][4] = {};
    gemm_ca(C, gHhi + (size_t)m0 * HIDN, gHlo + (size_t)m0 * HIDN, HIDN,
            Bh, Bl, HIDN, HIDN / 32, sm, tid);

    const int lane = tid & 31, warp = tid >> 5;
    const int wm = (warp & 1) * 32, wn = (warp >> 1) * 32;
    const int g_ = lane >> 2, tg = lane & 3;
    #pragma unroll
    for (int mi = 0; mi < 2; ++mi)
        #pragma unroll
        for (int j = 0; j < 4; ++j)
            #pragma unroll
            for (int e = 0; e < 4; ++e) {
                const int m = m0 + wm + mi * 16 + g_ + (e & 2) * 4;
                const int ng = n0 + wn + j * 8 + tg * 2 + (e & 1);
                float bias = (n0 < MLPH) ? b1a[ng] : b2a[ng - MLPH];
                float u = tanhf(C[mi][j][e] + bias);
                split_store(gUhi, gUlo, m * (2 * MLPH) + ng, u);
            }
}

// ------------------- stage 3a: p1/p2 GEMM, split-K=4, both branches -------------------
__global__ void __launch_bounds__(128) mlp_out_mma(int t)
{
    const int bs_t = g_bs[t];
    const int m0 = blockIdx.y * 64;
    if (m0 >= bs_t) return;
    const int n0 = blockIdx.x * 64;   // 0..255
    const int z  = blockIdx.z;        // 0..ZK-1, K slice of 256

    __shared__ __nv_bfloat16 sm[2][4][64 * SST];
    const int tid = threadIdx.x;
    const int kw = z * (MLPH / ZK);   // 0,256,512,768
    const int nkc = (MLPH / ZK) / 32; // 8

    float C1[2][4][4] = {};
    gemm_ca(C1, gUhi + (size_t)m0 * (2 * MLPH) + kw, gUlo + (size_t)m0 * (2 * MLPH) + kw, 2 * MLPH,
            gW1b_h + (size_t)n0 * MLPH + kw, gW1b_l + (size_t)n0 * MLPH + kw, MLPH,
            nkc, sm, tid);

    float C2[2][4][4] = {};
    gemm_ca(C2, gUhi + (size_t)m0 * (2 * MLPH) + MLPH + kw, gUlo + (size_t)m0 * (2 * MLPH) + MLPH + kw, 2 * MLPH,
            gW2b_h + (size_t)n0 * MLPH + kw, gW2b_l + (size_t)n0 * MLPH + kw, MLPH,
            nkc, sm, tid);

    const int lane = tid & 31, warp = tid >> 5;
    const int wm = (warp & 1) * 32, wn = (warp >> 1) * 32;
    const int g_ = lane >> 2, tg = lane & 3;
    #pragma unroll
    for (int mi = 0; mi < 2; ++mi)
        #pragma unroll
        for (int j = 0; j < 4; ++j)
            #pragma unroll
            for (int e = 0; e < 4; ++e) {
                const int m = m0 + wm + mi * 16 + g_ + (e & 2) * 4;
                const int n = n0 + wn + j * 8 + tg * 2 + (e & 1);
                g_pp[z][m][n]        = C1[mi][j][e];
                g_pp[z][m][n + OUTD] = C2[mi][j][e];
            }
}

// ------------------- stage 3b: combine split-K, reparam sample, scatter -------------------
__global__ void combine_kernel(
    const float* __restrict__ b1b, const float* __restrict__ b2b,
    const float* __restrict__ eps,
    float* __restrict__ out_p1, float* __restrict__ out_p2, int t)
{
    const int m = blockIdx.x;       // 0..511
    const int n = threadIdx.x;      // 0..255
    const int bs_t = g_bs[t];
    if (m >= bs_t) return;
    float p1 = b1b[n], p2 = b2b[n];
    #pragma unroll
    for (int z = 0; z < ZK; ++z) { p1 += g_pp[z][m][n]; p2 += g_pp[z][m][n + OUTD]; }
    float e  = eps[((size_t)t * B_SZ + m) * OUTD + n];
    float x  = p1 + expf(0.5f * p2) * e;
    split_store(gXhi, gXlo, m * OUTD + n, x);
    const int row = g_offs[t] + m;
    out_p1[(size_t)row * OUTD + n] = p1;
    out_p2[(size_t)row * OUTD + n] = p2;
}

// ------------------- launch -------------------
extern "C" void kernel_launch(void* const* d_in, const int* in_sizes, int n_in,
                              void* d_out, int out_size) {
    const int*   lengths = (const int*)  d_in[1];
    const float* eps     = (const float*)d_in[2];
    const float* W_ih    = (const float*)d_in[5];
    const float* b_ih    = (const float*)d_in[6];
    const float* b_hh    = (const float*)d_in[8];
    const float* W1a     = (const float*)d_in[9];
    const float* b1a     = (const float*)d_in[10];
    const float* W1b     = (const float*)d_in[11];
    const float* b1b     = (const float*)d_in[12];
    const float* W2a     = (const float*)d_in[13];
    const float* b2a     = (const float*)d_in[14];
    const float* W2b     = (const float*)d_in[15];
    const float* b2b     = (const float*)d_in[16];

    float* out = (float*)d_out;
    const long long N = (long long)out_size / (2 * OUTD + HIDN);
    float* out_p1 = out;
    float* out_p2 = out + N * OUTD;
    float* out_h  = out + 2LL * N * OUTD;

    const int GRU_SMEM = 2 * 8 * 64 * SST * (int)sizeof(__nv_bfloat16);  // 81920
    cudaFuncSetAttribute(gru_mma, cudaFuncAttributeMaxDynamicSharedMemorySize, GRU_SMEM);

    precompute_kernel<<<1, 256>>>(lengths);
    zero_x_kernel<<<512, 256>>>();
    convert_all_kernel<<<(N_ALL + 255) / 256, 256>>>(W_ih, W1a, W2a, W1b, W2b);

    for (int t = 0; t < T_MAXV; ++t) {
        gru_mma<<<dim3(16, 8), 128, GRU_SMEM>>>(b_ih, b_hh, out_h, t);
        mlp_hidden_mma<<<dim3(32, 8), 128>>>(b1a, b2a, t);
        mlp_out_mma<<<dim3(4, 8, ZK), 128>>>(t);
        combine_kernel<<<512, 256>>>(b1b, b2b, eps, out_p1, out_p2, t);
    }
}